// round 15
// baseline (speedup 1.0000x reference)
#include <cuda_runtime.h>
#include <cuda_fp16.h>
#include <math.h>
#include <cstdint>

// ---------------------------------------------------------------------------
// Problem constants
// ---------------------------------------------------------------------------
#define BB   8
#define CV   256
#define CT   512
#define TT   100
#define TPAD 128            // padded text rows for sim GEMM
#define NN_  4096           // H*W
#define ROWS (BB*NN_)       // 32768
#define TOPM 5

// ---------------------------------------------------------------------------
// Scratch (static device globals: allocation-free)
// ---------------------------------------------------------------------------
__device__ float  g_x   [ROWS * CV];        // ln1 output (fp32, residual path)
__device__ __half g_xt  [ROWS * CV];        // ln1 output (fp16, GEMM A)
__device__ float  g_gate[ROWS];             // sigmoid gate
__device__ __half g_q   [ROWS * CT];        // x@qw+qb (fp16)
__device__ float  g_qss [16 * ROWS];        // partial sum-of-squares of q rows
__device__ __half g_kn  [BB * TPAD * CT];   // l2norm(text) fp16, padded
__device__ __half g_tr  [BB * TT * CT];     // text fp16 (V GEMM A)
__device__ float  g_v   [BB * TT * CV];     // text@vw+vb (fp32)
__device__ int    g_pad [BB * TT];
__device__ float  g_sim [ROWS * TT];        // (q.k) * 1/||q||
__device__ float  g_y2  [ROWS * CV];        // ln2 output (fp32, residual)
__device__ __half g_y2t [ROWS * CV];        // ln2 output (fp16, GEMM A)
__device__ __half g_h   [ROWS * 4 * CV];    // gelu hidden (fp16)
// transposed fp16 weights ([N,K] K-major)
__device__ __half g_qwt [CT * CV];
__device__ __half g_vwt [CV * CT];
__device__ __half g_w1t [4*CV * CV];
__device__ __half g_w2t [CV * 4*CV];

// ---------------------------------------------------------------------------
// PTX helpers
// ---------------------------------------------------------------------------
__device__ __forceinline__ uint32_t smem_to_u32(const void* p) {
    uint32_t a;
    asm("{ .reg .u64 t; cvta.to.shared.u64 t, %1; cvt.u32.u64 %0, t; }"
        : "=r"(a) : "l"(p));
    return a;
}
__device__ __forceinline__ void cp16(uint32_t dst, const void* src, bool pred) {
    int sz = pred ? 16 : 0;
    asm volatile("cp.async.cg.shared.global [%0], [%1], 16, %2;\n"
        :: "r"(dst), "l"(src), "r"(sz));
}
__device__ __forceinline__ void cp16ca(uint32_t dst, const void* src, bool pred) {
    int sz = pred ? 16 : 0;
    asm volatile("cp.async.ca.shared.global [%0], [%1], 16, %2;\n"
        :: "r"(dst), "l"(src), "r"(sz));
}
__device__ __forceinline__ void mma16(float* c, const uint32_t* a, const uint32_t* b) {
    asm volatile(
        "mma.sync.aligned.m16n8k16.row.col.f32.f16.f16.f32 "
        "{%0,%1,%2,%3},{%4,%5,%6,%7},{%8,%9},{%0,%1,%2,%3};"
        : "+f"(c[0]), "+f"(c[1]), "+f"(c[2]), "+f"(c[3])
        : "r"(a[0]), "r"(a[1]), "r"(a[2]), "r"(a[3]), "r"(b[0]), "r"(b[1]));
}
__device__ __forceinline__ void ldsm4(uint32_t* r, uint32_t addr) {
    asm volatile("ldmatrix.sync.aligned.m8n8.x4.shared.b16 {%0,%1,%2,%3}, [%4];"
        : "=r"(r[0]), "=r"(r[1]), "=r"(r[2]), "=r"(r[3]) : "r"(addr));
}
__device__ __forceinline__ float wred(float v) {
    #pragma unroll
    for (int o = 16; o; o >>= 1) v += __shfl_xor_sync(0xffffffffu, v, o);
    return v;
}

// ---------------------------------------------------------------------------
// Prep kernel: blocks [0,768) weight transposes, [768, 768+4096) LN1+gate,
// then 128 text-prep blocks. 256 threads each.
// ---------------------------------------------------------------------------
#define TR_BLOCKS 768
#define LN1_BLOCKS (ROWS / 8)
#define TEXT_BLOCKS (BB * TPAD / 8)

__device__ __forceinline__ void tr_tile(const float* __restrict__ src,
                                        __half* __restrict__ dst,
                                        int Kd, int Nd, int bx, int by,
                                        float (*t)[33], int x, int y) {
    int k0 = by * 32, n0 = bx * 32;
    #pragma unroll
    for (int i = 0; i < 32; i += 8)
        t[y + i][x] = src[(long)(k0 + y + i) * Nd + n0 + x];
    __syncthreads();
    #pragma unroll
    for (int i = 0; i < 32; i += 8)
        dst[(long)(n0 + y + i) * Kd + k0 + x] = __float2half_rn(t[x][y + i]);
}

__global__ void prep_kernel(const float* __restrict__ vis,
                            const float* __restrict__ text,
                            const float* __restrict__ qw, const float* __restrict__ vw,
                            const float* __restrict__ w1, const float* __restrict__ w2,
                            const float* __restrict__ g, const float* __restrict__ b,
                            const float* __restrict__ gw, const float* __restrict__ gbp) {
    __shared__ float t[32][33];
    int lane = threadIdx.x & 31;
    if (blockIdx.x < TR_BLOCKS) {
        int id = blockIdx.x;
        int x = threadIdx.x & 31, y = threadIdx.x >> 5;
        if (id < 128)       tr_tile(qw, g_qwt, CV, CT, id & 15, id >> 4, t, x, y);
        else if (id < 256)  { id -= 128; tr_tile(vw, g_vwt, CT, CV, id & 7, id >> 3, t, x, y); }
        else if (id < 512)  { id -= 256; tr_tile(w1, g_w1t, CV, 4*CV, id & 31, id >> 5, t, x, y); }
        else                { id -= 512; tr_tile(w2, g_w2t, 4*CV, CV, id & 7, id >> 3, t, x, y); }
    } else if (blockIdx.x < TR_BLOCKS + LN1_BLOCKS) {
        int row = (blockIdx.x - TR_BLOCKS) * 8 + (threadIdx.x >> 5);
        const float4* vr = (const float4*)(vis + (long)row * CV);
        float4 v0 = vr[lane * 2], v1 = vr[lane * 2 + 1];
        float s = v0.x + v0.y + v0.z + v0.w + v1.x + v1.y + v1.z + v1.w;
        float mean = wred(s) * (1.f / CV);
        float d[8] = {v0.x-mean, v0.y-mean, v0.z-mean, v0.w-mean,
                      v1.x-mean, v1.y-mean, v1.z-mean, v1.w-mean};
        float sq = 0.f;
        #pragma unroll
        for (int e = 0; e < 8; e++) sq += d[e] * d[e];
        float rs = rsqrtf(wred(sq) * (1.f / CV) + 1e-5f);
        const float4* gr = (const float4*)g;  const float4* br = (const float4*)b;
        const float4* gwr = (const float4*)gw;
        float4 ga = gr[lane*2], gb4 = gr[lane*2+1], ba = br[lane*2], bb4 = br[lane*2+1];
        float4 wa = gwr[lane*2], wb = gwr[lane*2+1];
        float xv[8];
        xv[0]=d[0]*rs*ga.x+ba.x; xv[1]=d[1]*rs*ga.y+ba.y; xv[2]=d[2]*rs*ga.z+ba.z; xv[3]=d[3]*rs*ga.w+ba.w;
        xv[4]=d[4]*rs*gb4.x+bb4.x; xv[5]=d[5]*rs*gb4.y+bb4.y; xv[6]=d[6]*rs*gb4.z+bb4.z; xv[7]=d[7]*rs*gb4.w+bb4.w;
        float4* xo = (float4*)(g_x + (long)row * CV);
        xo[lane*2]   = make_float4(xv[0],xv[1],xv[2],xv[3]);
        xo[lane*2+1] = make_float4(xv[4],xv[5],xv[6],xv[7]);
        __half2* xto = (__half2*)(g_xt + (long)row * CV);
        xto[lane*4+0] = __floats2half2_rn(xv[0], xv[1]);
        xto[lane*4+1] = __floats2half2_rn(xv[2], xv[3]);
        xto[lane*4+2] = __floats2half2_rn(xv[4], xv[5]);
        xto[lane*4+3] = __floats2half2_rn(xv[6], xv[7]);
        float gp = xv[0]*wa.x+xv[1]*wa.y+xv[2]*wa.z+xv[3]*wa.w
                 + xv[4]*wb.x+xv[5]*wb.y+xv[6]*wb.z+xv[7]*wb.w;
        gp = wred(gp);
        if (lane == 0) g_gate[row] = 1.f / (1.f + expf(-(gp + gbp[0])));
    } else {
        int p = (blockIdx.x - TR_BLOCKS - LN1_BLOCKS) * 8 + (threadIdx.x >> 5);
        int bz = p >> 7, tt = p & (TPAD - 1);
        __half2* ko = (__half2*)(g_kn + (long)p * CT);
        if (tt >= TT) {
            #pragma unroll
            for (int j = 0; j < 4; j++) {
                ko[2*(lane + j*32)]     = __floats2half2_rn(0.f, 0.f);
                ko[2*(lane + j*32) + 1] = __floats2half2_rn(0.f, 0.f);
            }
            return;
        }
        const float4* tr = (const float4*)(text + ((long)bz * TT + tt) * CT);
        __half2* tro = (__half2*)(g_tr + ((long)bz * TT + tt) * CT);
        float4 v[4]; float sa = 0.f, ss = 0.f;
        #pragma unroll
        for (int j = 0; j < 4; j++) {
            v[j] = tr[lane + j * 32];
            sa += fabsf(v[j].x)+fabsf(v[j].y)+fabsf(v[j].z)+fabsf(v[j].w);
            ss += v[j].x*v[j].x + v[j].y*v[j].y + v[j].z*v[j].z + v[j].w*v[j].w;
        }
        sa = wred(sa); ss = wred(ss);
        if (lane == 0) g_pad[bz * TT + tt] = (sa <= 1e-6f) ? 1 : 0;
        float inv = 1.f / fmaxf(sqrtf(ss), 1e-6f);
        #pragma unroll
        for (int j = 0; j < 4; j++) {
            ko[2*(lane + j*32)]     = __floats2half2_rn(v[j].x*inv, v[j].y*inv);
            ko[2*(lane + j*32) + 1] = __floats2half2_rn(v[j].z*inv, v[j].w*inv);
            tro[2*(lane + j*32)]     = __floats2half2_rn(v[j].x, v[j].y);
            tro[2*(lane + j*32) + 1] = __floats2half2_rn(v[j].z, v[j].w);
        }
    }
}

// ---------------------------------------------------------------------------
// Shared GEMM machinery. CTA 128x128, BK=64, 8 warps (2x4), warp 64x32.
// 3-stage cp.async, one __syncthreads per chunk.
// Pointer-increment addressing; B (shared operand) loads use .ca.
// ---------------------------------------------------------------------------
#define SPITCH 72                         // halfs per smem row (144 B)
#define TILE_H (128 * SPITCH)
#define STAGE_H (2 * TILE_H)
#define NSTAGE 3
#define SMEM_BYTES (NSTAGE * STAGE_H * 2) // 110592 bytes

struct FragCtx {
    uint32_t sbase, aOff, bOff;
    int tid, wm, wn, lr, lc;
};

__device__ __forceinline__ void gemm_mainloop(
    const __half* __restrict__ A, const __half* __restrict__ Bt,
    int M, int N, int K, int m0, int n0, const FragCtx& fc,
    float acc[4][4][4])
{
    int tid = fc.tid;
    int nc = K >> 6;

    // hoisted per-thread load decode
    int r0 = tid >> 3;
    int k8 = (tid & 7) * 8;
    const __half* aPtr = A + (long)(m0 + r0) * K + k8;
    const __half* bPtr = Bt + (long)(n0 + r0) * K + k8;
    const long dK = (long)32 * K;
    bool pa[4], pb[4];
    uint32_t aoff[4], boff[4];
    #pragma unroll
    for (int i = 0; i < 4; i++) {
        pa[i] = (m0 + r0 + 32 * i) < M;
        pb[i] = (n0 + r0 + 32 * i) < N;
        aoff[i] = (uint32_t)((r0 + 32 * i) * SPITCH + k8) * 2u;
        boff[i] = aoff[i] + (uint32_t)TILE_H * 2u;
    }

    auto load_chunk = [&](int buf) {
        uint32_t s0 = fc.sbase + (uint32_t)(buf * STAGE_H) * 2u;
        #pragma unroll
        for (int i = 0; i < 4; i++)
            cp16(s0 + aoff[i], aPtr + dK * i, pa[i]);
        #pragma unroll
        for (int i = 0; i < 4; i++)
            cp16ca(s0 + boff[i], bPtr + dK * i, pb[i]);
        asm volatile("cp.async.commit_group;\n" ::: "memory");
        aPtr += 64; bPtr += 64;
    };

    load_chunk(0);
    if (nc > 1) load_chunk(1);
    else        asm volatile("cp.async.commit_group;\n" ::: "memory");

    for (int c = 0; c < nc; c++) {
        int buf = c % NSTAGE;
        asm volatile("cp.async.wait_group 1;\n" ::: "memory");
        __syncthreads();

        if (c + 2 < nc) load_chunk((c + 2) % NSTAGE);
        else asm volatile("cp.async.commit_group;\n" ::: "memory");

        uint32_t aBase = fc.sbase + (uint32_t)(buf * STAGE_H) * 2u + fc.aOff;
        uint32_t bBase = fc.sbase + (uint32_t)(buf * STAGE_H + TILE_H) * 2u + fc.bOff;

        #pragma unroll
        for (int ks = 0; ks < 4; ks++) {
            uint32_t kbyte = (uint32_t)(ks * 16 * 2);
            uint32_t af[4][4], bf[2][4];
            #pragma unroll
            for (int mi = 0; mi < 4; mi++)
                ldsm4(af[mi], aBase + (uint32_t)(mi * 16 * SPITCH * 2) + kbyte);
            #pragma unroll
            for (int np = 0; np < 2; np++)
                ldsm4(bf[np], bBase + (uint32_t)(np * 16 * SPITCH * 2) + kbyte);
            #pragma unroll
            for (int mi = 0; mi < 4; mi++)
                #pragma unroll
                for (int ni = 0; ni < 4; ni++)
                    mma16(acc[mi][ni], af[mi], &bf[ni >> 1][(ni & 1) * 2]);
        }
    }
}

__device__ __forceinline__ FragCtx make_ctx(uint32_t sbase) {
    FragCtx fc;
    int tid = threadIdx.x, wid = tid >> 5, lane = tid & 31;
    fc.tid = tid;
    fc.wm = wid & 1; fc.wn = wid >> 1;
    fc.lr = lane >> 2; fc.lc = lane & 3;
    int sel = lane >> 3, l8 = lane & 7;
    fc.sbase = sbase;
    fc.aOff = (uint32_t)(((fc.wm * 64 + (sel & 1) * 8 + l8) * SPITCH + (sel >> 1) * 8) * 2);
    fc.bOff = (uint32_t)(((fc.wn * 32 + (sel >> 1) * 8 + l8) * SPITCH + (sel & 1) * 8) * 2);
    return fc;
}

// ---------------------------------------------------------------------------
// Fused Q + V GEMM.
// ---------------------------------------------------------------------------
__global__ __launch_bounds__(256, 2) void qv_gemm(
    const float* __restrict__ qb, const float* __restrict__ vb)
{
    extern __shared__ __half smem[];
    FragCtx fc = make_ctx(smem_to_u32(smem));
    float acc[4][4][4];
    #pragma unroll
    for (int i = 0; i < 4; i++)
        #pragma unroll
        for (int j = 0; j < 4; j++)
            #pragma unroll
            for (int e = 0; e < 4; e++) acc[i][j][e] = 0.f;

    if (blockIdx.x < 1024) {
        int bx = blockIdx.x & 3, by = blockIdx.x >> 2;
        int m0 = by * 128, n0 = bx * 128;
        gemm_mainloop(g_xt, g_qwt, ROWS, CT, CV, m0, n0, fc, acc);
        #pragma unroll
        for (int mi = 0; mi < 4; mi++) {
            #pragma unroll
            for (int half_ = 0; half_ < 2; half_++) {
                int m = m0 + fc.wm * 64 + mi * 16 + fc.lr + half_ * 8;
                float ps = 0.f;
                #pragma unroll
                for (int ni = 0; ni < 4; ni++) {
                    int n = n0 + fc.wn * 32 + ni * 8 + 2 * fc.lc;
                    float x0 = acc[mi][ni][half_ * 2 + 0] + qb[n];
                    float x1 = acc[mi][ni][half_ * 2 + 1] + qb[n + 1];
                    ps += x0 * x0 + x1 * x1;
                    *(__half2*)(g_q + (long)m * CT + n) = __floats2half2_rn(x0, x1);
                }
                ps += __shfl_xor_sync(0xffffffffu, ps, 1);
                ps += __shfl_xor_sync(0xffffffffu, ps, 2);
                if (fc.lc == 0)
                    g_qss[(long)(bx * 4 + fc.wn) * ROWS + m] = ps;
            }
        }
    } else {
        int id2 = blockIdx.x - 1024;
        int bx = id2 & 1, by = id2 >> 1;
        int m0 = by * 128, n0 = bx * 128;
        gemm_mainloop(g_tr, g_vwt, BB * TT, CV, CT, m0, n0, fc, acc);
        #pragma unroll
        for (int mi = 0; mi < 4; mi++) {
            #pragma unroll
            for (int half_ = 0; half_ < 2; half_++) {
                int m = m0 + fc.wm * 64 + mi * 16 + fc.lr + half_ * 8;
                if (m >= BB * TT) continue;
                #pragma unroll
                for (int ni = 0; ni < 4; ni++) {
                    int n = n0 + fc.wn * 32 + ni * 8 + 2 * fc.lc;
                    g_v[(long)m * CV + n]     = acc[mi][ni][half_ * 2 + 0] + vb[n];
                    g_v[(long)m * CV + n + 1] = acc[mi][ni][half_ * 2 + 1] + vb[n + 1];
                }
            }
        }
    }
}

// ---------------------------------------------------------------------------
// mma_gemm template: sim (EPI 3), MLP1 (EPI 1), MLP2 (EPI 2)
// ---------------------------------------------------------------------------
template<int EPI>
__global__ __launch_bounds__(256, 2) void mma_gemm(
    const __half* __restrict__ A, const __half* __restrict__ Bt,
    const float* __restrict__ bias, const float* __restrict__ R,
    void* __restrict__ Cv, int M, int N, int K,
    int ldc, int n_store, long sA, long sB, long sC)
{
    extern __shared__ __half smem[];
    FragCtx fc = make_ctx(smem_to_u32(smem));

    A  += (long)blockIdx.z * sA;
    Bt += (long)blockIdx.z * sB;
    float*  Cf = (float*)Cv  + (long)blockIdx.z * sC;
    __half* Ch = (__half*)Cv + (long)blockIdx.z * sC;
    const float* Rp = (EPI == 2) ? (R + (long)blockIdx.z * sC)
                    : (EPI == 3) ? (R + (long)blockIdx.z * M) : R;

    int m0 = blockIdx.y * 128, n0 = blockIdx.x * 128;

    float acc[4][4][4];
    #pragma unroll
    for (int i = 0; i < 4; i++)
        #pragma unroll
        for (int j = 0; j < 4; j++)
            #pragma unroll
            for (int e = 0; e < 4; e++) acc[i][j][e] = 0.f;

    gemm_mainloop(A, Bt, M, N, K, m0, n0, fc, acc);

    // ---- EPI 3: stage 16 qss partials per row into smem scratch ----
    float* qs = (float*)smem;
    if (EPI == 3) {
        __syncthreads();
        #pragma unroll
        for (int i = 0; i < 8; i++) {
            int idx = fc.tid + 256 * i;         // 0..2047
            int p = idx >> 7, row = idx & 127;
            qs[row * 17 + p] = Rp[(long)p * ROWS + m0 + row];
        }
        __syncthreads();
    }

    #pragma unroll
    for (int mi = 0; mi < 4; mi++) {
        #pragma unroll
        for (int half_ = 0; half_ < 2; half_++) {
            int m = m0 + fc.wm * 64 + mi * 16 + fc.lr + half_ * 8;
            if (m >= M) continue;
            float rscale = 0.f;
            if (EPI == 3) {
                float ss = 0.f;
                #pragma unroll
                for (int i = 0; i < 16; i++) ss += qs[(m - m0) * 17 + i];
                rscale = 1.f / fmaxf(sqrtf(ss), 1e-6f);
            }
            #pragma unroll
            for (int ni = 0; ni < 4; ni++) {
                int n = n0 + fc.wn * 32 + ni * 8 + 2 * fc.lc;
                if (EPI == 1) {
                    float x0 = acc[mi][ni][half_ * 2 + 0] + bias[n];
                    float x1 = acc[mi][ni][half_ * 2 + 1] + bias[n + 1];
                    x0 = 0.5f * x0 * (1.f + erff(x0 * 0.70710678118654752f));
                    x1 = 0.5f * x1 * (1.f + erff(x1 * 0.70710678118654752f));
                    *(__half2*)(Ch + (long)m * ldc + n) = __floats2half2_rn(x0, x1);
                } else {
                    #pragma unroll
                    for (int e = 0; e < 2; e++) {
                        int ne = n + e;
                        if (ne >= n_store) continue;
                        float x = acc[mi][ni][half_ * 2 + e];
                        if (EPI == 2) x += bias[ne] + Rp[(long)m * ldc + ne];
                        if (EPI == 3) x *= rscale;
                        Cf[(long)m * ldc + ne] = x;
                    }
                }
            }
        }
    }
}

// ---------------------------------------------------------------------------
// top-5 + softmax + gather + gate + residual + fused LN2 (one warp per pixel)
// float4 sim loads (TT=100 = 25 float4/row); redux.sync argmax.
// ---------------------------------------------------------------------------
__global__ void topk_ln2_kernel(const float* __restrict__ logit_scale,
                                const float* __restrict__ alpha_p,
                                const float* __restrict__ g2,
                                const float* __restrict__ b2) {
    int warp = (blockIdx.x * blockDim.x + threadIdx.x) >> 5;
    int lane = threadIdx.x & 31;
    int b = warp >> 12;

    float ls = logit_scale[0];
    float scale = expf(fminf(fmaxf(ls, -2.f), 2.f)) * rsqrtf((float)CT);
    float alpha = alpha_p[0];

    // one LDG.128 per lane covers the whole 100-float row (lanes 0..24)
    float vals[4];
    if (lane < 25) {
        float4 v4 = *(const float4*)(g_sim + (long)warp * TT + lane * 4);
        vals[0] = v4.x * scale; vals[1] = v4.y * scale;
        vals[2] = v4.z * scale; vals[3] = v4.w * scale;
    } else {
        vals[0] = vals[1] = vals[2] = vals[3] = -INFINITY;
    }

    float wv[TOPM]; int wi_[TOPM];
    #pragma unroll
    for (int m = 0; m < TOPM; m++) {
        float bv = vals[0]; int bs = 0;
        #pragma unroll
        for (int i = 1; i < 4; i++)
            if (vals[i] > bv) { bv = vals[i]; bs = i; }     // first max = lowest t
        uint32_t u = __float_as_uint(bv);
        uint32_t key = u ^ ((uint32_t)((int)u >> 31) | 0x80000000u);
        uint32_t wkey = __reduce_max_sync(0xffffffffu, key);
        uint32_t gidx = (key == wkey) ? (uint32_t)(lane * 4 + bs) : 0xffffffffu;
        uint32_t widx = __reduce_min_sync(0xffffffffu, gidx);   // = min token idx
        wv[m] = __uint_as_float((wkey & 0x80000000u) ? (wkey ^ 0x80000000u) : ~wkey);
        wi_[m] = (int)widx;
        if ((widx >> 2) == (uint32_t)lane) vals[widx & 3u] = -INFINITY;
    }

    float mx = -INFINITY;
    #pragma unroll
    for (int m = 0; m < TOPM; m++) {
        if (g_pad[b * TT + wi_[m]]) wv[m] = -INFINITY;
        mx = fmaxf(mx, wv[m]);
    }
    float e[TOPM]; float se = 0.f;
    #pragma unroll
    for (int m = 0; m < TOPM; m++) {
        e[m] = (wv[m] == -INFINITY) ? 0.f : expf(wv[m] - mx);
        se += e[m];
    }
    float inv = 1.f / se;
    float ag = alpha * g_gate[warp];

    // hoisted gather base pointers + weights
    const float* vp[TOPM]; float wgt[TOPM];
    #pragma unroll
    for (int m = 0; m < TOPM; m++) {
        vp[m] = g_v + (long)(b * TT + wi_[m]) * CV;
        wgt[m] = e[m] * inv;
    }

    long rowoff = (long)warp * CV;
    float yv[8];
    #pragma unroll
    for (int j = 0; j < 8; j++) {
        int c = lane + 32 * j;
        float a2 = 0.f;
        #pragma unroll
        for (int m = 0; m < TOPM; m++)
            a2 = fmaf(wgt[m], vp[m][c], a2);
        yv[j] = g_x[rowoff + c] + ag * a2;
    }
    // fused LayerNorm2
    float s = 0.f;
    #pragma unroll
    for (int j = 0; j < 8; j++) s += yv[j];
    float mean = wred(s) * (1.f / CV);
    float sq = 0.f;
    #pragma unroll
    for (int j = 0; j < 8; j++) { float d = yv[j] - mean; sq += d * d; }
    float rs = rsqrtf(wred(sq) * (1.f / CV) + 1e-5f);
    #pragma unroll
    for (int j = 0; j < 8; j++) {
        int c = lane + 32 * j;
        float y2 = (yv[j] - mean) * rs * g2[c] + b2[c];
        g_y2 [rowoff + c] = y2;
        g_y2t[rowoff + c] = __float2half_rn(y2);
    }
}

// ---------------------------------------------------------------------------
// Launch
// ---------------------------------------------------------------------------
static void* symaddr(const void* sym) {
    void* p = nullptr;
    cudaGetSymbolAddress(&p, sym);
    return p;
}

extern "C" void kernel_launch(void* const* d_in, const int* in_sizes, int n_in,
                              void* d_out, int out_size) {
    const float* visual = (const float*)d_in[0];
    const float* text   = (const float*)d_in[1];
    const float* ln1_g  = (const float*)d_in[2];
    const float* ln1_b  = (const float*)d_in[3];
    const float* qw     = (const float*)d_in[4];
    const float* qb     = (const float*)d_in[5];
    const float* vw     = (const float*)d_in[6];
    const float* vb     = (const float*)d_in[7];
    const float* gate_w = (const float*)d_in[8];
    const float* gate_b = (const float*)d_in[9];
    const float* lscale = (const float*)d_in[10];
    const float* alpha  = (const float*)d_in[11];
    const float* ln2_g  = (const float*)d_in[12];
    const float* ln2_b  = (const float*)d_in[13];
    const float* w1     = (const float*)d_in[14];
    const float* b1     = (const float*)d_in[15];
    const float* w2     = (const float*)d_in[16];
    const float* b2     = (const float*)d_in[17];
    float* out = (float*)d_out;

    __half* pq   = (__half*)symaddr(g_q);
    float*  pqss = (float*) symaddr(g_qss);
    __half* pkn  = (__half*)symaddr(g_kn);
    float*  ps   = (float*) symaddr(g_sim);
    float*  py2  = (float*) symaddr(g_y2);
    __half* py2t = (__half*)symaddr(g_y2t);
    __half* ph   = (__half*)symaddr(g_h);
    __half* pw1t = (__half*)symaddr(g_w1t);
    __half* pw2t = (__half*)symaddr(g_w2t);

    cudaFuncSetAttribute(qv_gemm,     cudaFuncAttributeMaxDynamicSharedMemorySize, SMEM_BYTES);
    cudaFuncSetAttribute(mma_gemm<1>, cudaFuncAttributeMaxDynamicSharedMemorySize, SMEM_BYTES);
    cudaFuncSetAttribute(mma_gemm<2>, cudaFuncAttributeMaxDynamicSharedMemorySize, SMEM_BYTES);
    cudaFuncSetAttribute(mma_gemm<3>, cudaFuncAttributeMaxDynamicSharedMemorySize, SMEM_BYTES);

    // 1. prep: weight transposes + LN1/gate + text prep (one launch)
    prep_kernel<<<TR_BLOCKS + LN1_BLOCKS + TEXT_BLOCKS, 256>>>(
        visual, text, qw, vw, w1, w2, ln1_g, ln1_b, gate_w, gate_b);

    // 2. Q (+qss) and V GEMMs fused in one launch
    qv_gemm<<<1024 + 14, 256, SMEM_BYTES>>>(qb, vb);

    // 3. sim = (q @ k^T) * rsqrt(sum qss)  (4096 x 100(->128) x 512, batched)
    mma_gemm<3><<<dim3(1, NN_/128, BB), 256, SMEM_BYTES>>>(
        pq, pkn, nullptr, pqss, ps, NN_, TPAD, CT, TT, TT,
        (long)NN_*CT, (long)TPAD*CT, (long)NN_*TT);

    // 4. top-5 + softmax + gather + gate + residual + LN2
    topk_ln2_kernel<<<ROWS/8, 256>>>(lscale, alpha, ln2_g, ln2_b);

    // 5. h = gelu(y2 @ w1 + b1) -> fp16   (32768 x 1024 x 256)
    mma_gemm<1><<<dim3(4*CV/128, ROWS/128, 1), 256, SMEM_BYTES>>>(
        py2t, pw1t, b1, nullptr, ph, ROWS, 4*CV, CV, 4*CV, 4*CV, 0, 0, 0);

    // 6. out = y2 + h @ w2 + b2 -> fp32   (32768 x 256 x 1024)
    mma_gemm<2><<<dim3(CV/128, ROWS/128, 1), 256, SMEM_BYTES>>>(
        ph, pw2t, b2, py2, out, ROWS, CV, 4*CV, CV, CV, 0, 0, 0);
}

// round 16
// speedup vs baseline: 1.0150x; 1.0150x over previous
#include <cuda_runtime.h>
#include <cuda_fp16.h>
#include <math.h>
#include <cstdint>

// ---------------------------------------------------------------------------
// Problem constants
// ---------------------------------------------------------------------------
#define BB   8
#define CV   256
#define CT   512
#define TT   100
#define TPAD 128            // padded text rows for sim GEMM
#define NN_  4096           // H*W
#define ROWS (BB*NN_)       // 32768
#define TOPM 5

// ---------------------------------------------------------------------------
// Scratch (static device globals: allocation-free)
// ---------------------------------------------------------------------------
__device__ float  g_x   [ROWS * CV];        // ln1 output (fp32, residual path)
__device__ __half g_xt  [ROWS * CV];        // ln1 output (fp16, GEMM A)
__device__ float  g_gate[ROWS];             // sigmoid gate
__device__ __half g_q   [ROWS * CT];        // x@qw+qb (fp16)
__device__ float  g_qss [16 * ROWS];        // partial sum-of-squares of q rows
__device__ __half g_kn  [BB * TPAD * CT];   // l2norm(text) fp16, padded
__device__ __half g_tr  [BB * TT * CT];     // text fp16 (V GEMM A)
__device__ float  g_v   [BB * TT * CV];     // text@vw+vb (fp32)
__device__ int    g_pad [BB * TT];
__device__ float  g_sim [ROWS * TT];        // (q.k) * 1/||q||
__device__ float  g_y2  [ROWS * CV];        // ln2 output (fp32, residual)
__device__ __half g_y2t [ROWS * CV];        // ln2 output (fp16, GEMM A)
__device__ __half g_h   [ROWS * 4 * CV];    // gelu hidden (fp16)
// transposed fp16 weights ([N,K] K-major)
__device__ __half g_qwt [CT * CV];
__device__ __half g_vwt [CV * CT];
__device__ __half g_w1t [4*CV * CV];
__device__ __half g_w2t [CV * 4*CV];

// ---------------------------------------------------------------------------
// PTX helpers
// ---------------------------------------------------------------------------
__device__ __forceinline__ uint32_t smem_to_u32(const void* p) {
    uint32_t a;
    asm("{ .reg .u64 t; cvta.to.shared.u64 t, %1; cvt.u32.u64 %0, t; }"
        : "=r"(a) : "l"(p));
    return a;
}
__device__ __forceinline__ void cp16(uint32_t dst, const void* src, bool pred) {
    int sz = pred ? 16 : 0;
    asm volatile("cp.async.cg.shared.global [%0], [%1], 16, %2;\n"
        :: "r"(dst), "l"(src), "r"(sz));
}
__device__ __forceinline__ void mma16(float* c, const uint32_t* a, const uint32_t* b) {
    asm volatile(
        "mma.sync.aligned.m16n8k16.row.col.f32.f16.f16.f32 "
        "{%0,%1,%2,%3},{%4,%5,%6,%7},{%8,%9},{%0,%1,%2,%3};"
        : "+f"(c[0]), "+f"(c[1]), "+f"(c[2]), "+f"(c[3])
        : "r"(a[0]), "r"(a[1]), "r"(a[2]), "r"(a[3]), "r"(b[0]), "r"(b[1]));
}
__device__ __forceinline__ void ldsm4(uint32_t* r, uint32_t addr) {
    asm volatile("ldmatrix.sync.aligned.m8n8.x4.shared.b16 {%0,%1,%2,%3}, [%4];"
        : "=r"(r[0]), "=r"(r[1]), "=r"(r[2]), "=r"(r[3]) : "r"(addr));
}
__device__ __forceinline__ float wred(float v) {
    #pragma unroll
    for (int o = 16; o; o >>= 1) v += __shfl_xor_sync(0xffffffffu, v, o);
    return v;
}

// ---------------------------------------------------------------------------
// Prep kernel: blocks [0,768) weight transposes, [768, 768+4096) LN1+gate,
// then 128 text-prep blocks. 256 threads each.
// ---------------------------------------------------------------------------
#define TR_BLOCKS 768
#define LN1_BLOCKS (ROWS / 8)
#define TEXT_BLOCKS (BB * TPAD / 8)

__device__ __forceinline__ void tr_tile(const float* __restrict__ src,
                                        __half* __restrict__ dst,
                                        int Kd, int Nd, int bx, int by,
                                        float (*t)[33], int x, int y) {
    int k0 = by * 32, n0 = bx * 32;
    #pragma unroll
    for (int i = 0; i < 32; i += 8)
        t[y + i][x] = src[(long)(k0 + y + i) * Nd + n0 + x];
    __syncthreads();
    #pragma unroll
    for (int i = 0; i < 32; i += 8)
        dst[(long)(n0 + y + i) * Kd + k0 + x] = __float2half_rn(t[x][y + i]);
}

__global__ void prep_kernel(const float* __restrict__ vis,
                            const float* __restrict__ text,
                            const float* __restrict__ qw, const float* __restrict__ vw,
                            const float* __restrict__ w1, const float* __restrict__ w2,
                            const float* __restrict__ g, const float* __restrict__ b,
                            const float* __restrict__ gw, const float* __restrict__ gbp) {
    __shared__ float t[32][33];
    int lane = threadIdx.x & 31;
    if (blockIdx.x < TR_BLOCKS) {
        int id = blockIdx.x;
        int x = threadIdx.x & 31, y = threadIdx.x >> 5;
        if (id < 128)       tr_tile(qw, g_qwt, CV, CT, id & 15, id >> 4, t, x, y);
        else if (id < 256)  { id -= 128; tr_tile(vw, g_vwt, CT, CV, id & 7, id >> 3, t, x, y); }
        else if (id < 512)  { id -= 256; tr_tile(w1, g_w1t, CV, 4*CV, id & 31, id >> 5, t, x, y); }
        else                { id -= 512; tr_tile(w2, g_w2t, 4*CV, CV, id & 7, id >> 3, t, x, y); }
    } else if (blockIdx.x < TR_BLOCKS + LN1_BLOCKS) {
        int row = (blockIdx.x - TR_BLOCKS) * 8 + (threadIdx.x >> 5);
        const float4* vr = (const float4*)(vis + (long)row * CV);
        float4 v0 = vr[lane * 2], v1 = vr[lane * 2 + 1];
        float s = v0.x + v0.y + v0.z + v0.w + v1.x + v1.y + v1.z + v1.w;
        float mean = wred(s) * (1.f / CV);
        float d[8] = {v0.x-mean, v0.y-mean, v0.z-mean, v0.w-mean,
                      v1.x-mean, v1.y-mean, v1.z-mean, v1.w-mean};
        float sq = 0.f;
        #pragma unroll
        for (int e = 0; e < 8; e++) sq += d[e] * d[e];
        float rs = rsqrtf(wred(sq) * (1.f / CV) + 1e-5f);
        const float4* gr = (const float4*)g;  const float4* br = (const float4*)b;
        const float4* gwr = (const float4*)gw;
        float4 ga = gr[lane*2], gb4 = gr[lane*2+1], ba = br[lane*2], bb4 = br[lane*2+1];
        float4 wa = gwr[lane*2], wb = gwr[lane*2+1];
        float xv[8];
        xv[0]=d[0]*rs*ga.x+ba.x; xv[1]=d[1]*rs*ga.y+ba.y; xv[2]=d[2]*rs*ga.z+ba.z; xv[3]=d[3]*rs*ga.w+ba.w;
        xv[4]=d[4]*rs*gb4.x+bb4.x; xv[5]=d[5]*rs*gb4.y+bb4.y; xv[6]=d[6]*rs*gb4.z+bb4.z; xv[7]=d[7]*rs*gb4.w+bb4.w;
        float4* xo = (float4*)(g_x + (long)row * CV);
        xo[lane*2]   = make_float4(xv[0],xv[1],xv[2],xv[3]);
        xo[lane*2+1] = make_float4(xv[4],xv[5],xv[6],xv[7]);
        __half2* xto = (__half2*)(g_xt + (long)row * CV);
        xto[lane*4+0] = __floats2half2_rn(xv[0], xv[1]);
        xto[lane*4+1] = __floats2half2_rn(xv[2], xv[3]);
        xto[lane*4+2] = __floats2half2_rn(xv[4], xv[5]);
        xto[lane*4+3] = __floats2half2_rn(xv[6], xv[7]);
        float gp = xv[0]*wa.x+xv[1]*wa.y+xv[2]*wa.z+xv[3]*wa.w
                 + xv[4]*wb.x+xv[5]*wb.y+xv[6]*wb.z+xv[7]*wb.w;
        gp = wred(gp);
        if (lane == 0) g_gate[row] = 1.f / (1.f + expf(-(gp + gbp[0])));
    } else {
        int p = (blockIdx.x - TR_BLOCKS - LN1_BLOCKS) * 8 + (threadIdx.x >> 5);
        int bz = p >> 7, tt = p & (TPAD - 1);
        __half2* ko = (__half2*)(g_kn + (long)p * CT);
        if (tt >= TT) {
            #pragma unroll
            for (int j = 0; j < 4; j++) {
                ko[2*(lane + j*32)]     = __floats2half2_rn(0.f, 0.f);
                ko[2*(lane + j*32) + 1] = __floats2half2_rn(0.f, 0.f);
            }
            return;
        }
        const float4* tr = (const float4*)(text + ((long)bz * TT + tt) * CT);
        __half2* tro = (__half2*)(g_tr + ((long)bz * TT + tt) * CT);
        float4 v[4]; float sa = 0.f, ss = 0.f;
        #pragma unroll
        for (int j = 0; j < 4; j++) {
            v[j] = tr[lane + j * 32];
            sa += fabsf(v[j].x)+fabsf(v[j].y)+fabsf(v[j].z)+fabsf(v[j].w);
            ss += v[j].x*v[j].x + v[j].y*v[j].y + v[j].z*v[j].z + v[j].w*v[j].w;
        }
        sa = wred(sa); ss = wred(ss);
        if (lane == 0) g_pad[bz * TT + tt] = (sa <= 1e-6f) ? 1 : 0;
        float inv = 1.f / fmaxf(sqrtf(ss), 1e-6f);
        #pragma unroll
        for (int j = 0; j < 4; j++) {
            ko[2*(lane + j*32)]     = __floats2half2_rn(v[j].x*inv, v[j].y*inv);
            ko[2*(lane + j*32) + 1] = __floats2half2_rn(v[j].z*inv, v[j].w*inv);
            tro[2*(lane + j*32)]     = __floats2half2_rn(v[j].x, v[j].y);
            tro[2*(lane + j*32) + 1] = __floats2half2_rn(v[j].z, v[j].w);
        }
    }
}

// ---------------------------------------------------------------------------
// Shared GEMM machinery. CTA 128x128, BK=64, 8 warps (2x4), warp 64x32.
// 3-stage cp.async, one __syncthreads per chunk.
// Pointer-increment addressing: all per-chunk address math hoisted.
// ---------------------------------------------------------------------------
#define SPITCH 72                         // halfs per smem row (144 B)
#define TILE_H (128 * SPITCH)
#define STAGE_H (2 * TILE_H)
#define NSTAGE 3
#define SMEM_BYTES (NSTAGE * STAGE_H * 2) // 110592 bytes

struct FragCtx {
    uint32_t sbase, aOff, bOff;
    int tid, wm, wn, lr, lc;
};

__device__ __forceinline__ void gemm_mainloop(
    const __half* __restrict__ A, const __half* __restrict__ Bt,
    int M, int N, int K, int m0, int n0, const FragCtx& fc,
    float acc[4][4][4])
{
    int tid = fc.tid;
    int nc = K >> 6;

    // hoisted per-thread load decode
    int r0 = tid >> 3;
    int k8 = (tid & 7) * 8;
    const __half* aPtr = A + (long)(m0 + r0) * K + k8;
    const __half* bPtr = Bt + (long)(n0 + r0) * K + k8;
    const long dK = (long)32 * K;
    bool pa[4], pb[4];
    uint32_t aoff[4], boff[4];
    #pragma unroll
    for (int i = 0; i < 4; i++) {
        pa[i] = (m0 + r0 + 32 * i) < M;
        pb[i] = (n0 + r0 + 32 * i) < N;
        aoff[i] = (uint32_t)((r0 + 32 * i) * SPITCH + k8) * 2u;
        boff[i] = aoff[i] + (uint32_t)TILE_H * 2u;
    }

    auto load_chunk = [&](int buf) {
        uint32_t s0 = fc.sbase + (uint32_t)(buf * STAGE_H) * 2u;
        #pragma unroll
        for (int i = 0; i < 4; i++)
            cp16(s0 + aoff[i], aPtr + dK * i, pa[i]);
        #pragma unroll
        for (int i = 0; i < 4; i++)
            cp16(s0 + boff[i], bPtr + dK * i, pb[i]);
        asm volatile("cp.async.commit_group;\n" ::: "memory");
        aPtr += 64; bPtr += 64;
    };

    load_chunk(0);
    if (nc > 1) load_chunk(1);
    else        asm volatile("cp.async.commit_group;\n" ::: "memory");

    for (int c = 0; c < nc; c++) {
        int buf = c % NSTAGE;
        asm volatile("cp.async.wait_group 1;\n" ::: "memory");
        __syncthreads();

        if (c + 2 < nc) load_chunk((c + 2) % NSTAGE);
        else asm volatile("cp.async.commit_group;\n" ::: "memory");

        uint32_t aBase = fc.sbase + (uint32_t)(buf * STAGE_H) * 2u + fc.aOff;
        uint32_t bBase = fc.sbase + (uint32_t)(buf * STAGE_H + TILE_H) * 2u + fc.bOff;

        #pragma unroll
        for (int ks = 0; ks < 4; ks++) {
            uint32_t kbyte = (uint32_t)(ks * 16 * 2);
            uint32_t af[4][4], bf[2][4];
            #pragma unroll
            for (int mi = 0; mi < 4; mi++)
                ldsm4(af[mi], aBase + (uint32_t)(mi * 16 * SPITCH * 2) + kbyte);
            #pragma unroll
            for (int np = 0; np < 2; np++)
                ldsm4(bf[np], bBase + (uint32_t)(np * 16 * SPITCH * 2) + kbyte);
            #pragma unroll
            for (int mi = 0; mi < 4; mi++)
                #pragma unroll
                for (int ni = 0; ni < 4; ni++)
                    mma16(acc[mi][ni], af[mi], &bf[ni >> 1][(ni & 1) * 2]);
        }
    }
}

__device__ __forceinline__ FragCtx make_ctx(uint32_t sbase) {
    FragCtx fc;
    int tid = threadIdx.x, wid = tid >> 5, lane = tid & 31;
    fc.tid = tid;
    fc.wm = wid & 1; fc.wn = wid >> 1;
    fc.lr = lane >> 2; fc.lc = lane & 3;
    int sel = lane >> 3, l8 = lane & 7;
    fc.sbase = sbase;
    fc.aOff = (uint32_t)(((fc.wm * 64 + (sel & 1) * 8 + l8) * SPITCH + (sel >> 1) * 8) * 2);
    fc.bOff = (uint32_t)(((fc.wn * 32 + (sel >> 1) * 8 + l8) * SPITCH + (sel & 1) * 8) * 2);
    return fc;
}

// ---------------------------------------------------------------------------
// Fused Q + V GEMM.
// ---------------------------------------------------------------------------
__global__ __launch_bounds__(256, 2) void qv_gemm(
    const float* __restrict__ qb, const float* __restrict__ vb)
{
    extern __shared__ __half smem[];
    FragCtx fc = make_ctx(smem_to_u32(smem));
    float acc[4][4][4];
    #pragma unroll
    for (int i = 0; i < 4; i++)
        #pragma unroll
        for (int j = 0; j < 4; j++)
            #pragma unroll
            for (int e = 0; e < 4; e++) acc[i][j][e] = 0.f;

    if (blockIdx.x < 1024) {
        int bx = blockIdx.x & 3, by = blockIdx.x >> 2;
        int m0 = by * 128, n0 = bx * 128;
        gemm_mainloop(g_xt, g_qwt, ROWS, CT, CV, m0, n0, fc, acc);
        #pragma unroll
        for (int mi = 0; mi < 4; mi++) {
            #pragma unroll
            for (int half_ = 0; half_ < 2; half_++) {
                int m = m0 + fc.wm * 64 + mi * 16 + fc.lr + half_ * 8;
                float ps = 0.f;
                #pragma unroll
                for (int ni = 0; ni < 4; ni++) {
                    int n = n0 + fc.wn * 32 + ni * 8 + 2 * fc.lc;
                    float x0 = acc[mi][ni][half_ * 2 + 0] + qb[n];
                    float x1 = acc[mi][ni][half_ * 2 + 1] + qb[n + 1];
                    ps += x0 * x0 + x1 * x1;
                    *(__half2*)(g_q + (long)m * CT + n) = __floats2half2_rn(x0, x1);
                }
                ps += __shfl_xor_sync(0xffffffffu, ps, 1);
                ps += __shfl_xor_sync(0xffffffffu, ps, 2);
                if (fc.lc == 0)
                    g_qss[(long)(bx * 4 + fc.wn) * ROWS + m] = ps;
            }
        }
    } else {
        int id2 = blockIdx.x - 1024;
        int bx = id2 & 1, by = id2 >> 1;
        int m0 = by * 128, n0 = bx * 128;
        gemm_mainloop(g_tr, g_vwt, BB * TT, CV, CT, m0, n0, fc, acc);
        #pragma unroll
        for (int mi = 0; mi < 4; mi++) {
            #pragma unroll
            for (int half_ = 0; half_ < 2; half_++) {
                int m = m0 + fc.wm * 64 + mi * 16 + fc.lr + half_ * 8;
                if (m >= BB * TT) continue;
                #pragma unroll
                for (int ni = 0; ni < 4; ni++) {
                    int n = n0 + fc.wn * 32 + ni * 8 + 2 * fc.lc;
                    g_v[(long)m * CV + n]     = acc[mi][ni][half_ * 2 + 0] + vb[n];
                    g_v[(long)m * CV + n + 1] = acc[mi][ni][half_ * 2 + 1] + vb[n + 1];
                }
            }
        }
    }
}

// ---------------------------------------------------------------------------
// mma_gemm template: sim (EPI 3), MLP1 (EPI 1), MLP2 (EPI 2)
// ---------------------------------------------------------------------------
template<int EPI>
__global__ __launch_bounds__(256, 2) void mma_gemm(
    const __half* __restrict__ A, const __half* __restrict__ Bt,
    const float* __restrict__ bias, const float* __restrict__ R,
    void* __restrict__ Cv, int M, int N, int K,
    int ldc, int n_store, long sA, long sB, long sC)
{
    extern __shared__ __half smem[];
    FragCtx fc = make_ctx(smem_to_u32(smem));

    A  += (long)blockIdx.z * sA;
    Bt += (long)blockIdx.z * sB;
    float*  Cf = (float*)Cv  + (long)blockIdx.z * sC;
    __half* Ch = (__half*)Cv + (long)blockIdx.z * sC;
    const float* Rp = (EPI == 2) ? (R + (long)blockIdx.z * sC)
                    : (EPI == 3) ? (R + (long)blockIdx.z * M) : R;

    int m0 = blockIdx.y * 128, n0 = blockIdx.x * 128;

    float acc[4][4][4];
    #pragma unroll
    for (int i = 0; i < 4; i++)
        #pragma unroll
        for (int j = 0; j < 4; j++)
            #pragma unroll
            for (int e = 0; e < 4; e++) acc[i][j][e] = 0.f;

    gemm_mainloop(A, Bt, M, N, K, m0, n0, fc, acc);

    // ---- EPI 3: stage 16 qss partials per row into smem scratch ----
    float* qs = (float*)smem;
    if (EPI == 3) {
        __syncthreads();
        #pragma unroll
        for (int i = 0; i < 8; i++) {
            int idx = fc.tid + 256 * i;         // 0..2047
            int p = idx >> 7, row = idx & 127;
            qs[row * 17 + p] = Rp[(long)p * ROWS + m0 + row];
        }
        __syncthreads();
    }

    #pragma unroll
    for (int mi = 0; mi < 4; mi++) {
        #pragma unroll
        for (int half_ = 0; half_ < 2; half_++) {
            int m = m0 + fc.wm * 64 + mi * 16 + fc.lr + half_ * 8;
            if (m >= M) continue;
            float rscale = 0.f;
            if (EPI == 3) {
                float ss = 0.f;
                #pragma unroll
                for (int i = 0; i < 16; i++) ss += qs[(m - m0) * 17 + i];
                rscale = 1.f / fmaxf(sqrtf(ss), 1e-6f);
            }
            #pragma unroll
            for (int ni = 0; ni < 4; ni++) {
                int n = n0 + fc.wn * 32 + ni * 8 + 2 * fc.lc;
                if (EPI == 1) {
                    float x0 = acc[mi][ni][half_ * 2 + 0] + bias[n];
                    float x1 = acc[mi][ni][half_ * 2 + 1] + bias[n + 1];
                    x0 = 0.5f * x0 * (1.f + erff(x0 * 0.70710678118654752f));
                    x1 = 0.5f * x1 * (1.f + erff(x1 * 0.70710678118654752f));
                    *(__half2*)(Ch + (long)m * ldc + n) = __floats2half2_rn(x0, x1);
                } else {
                    #pragma unroll
                    for (int e = 0; e < 2; e++) {
                        int ne = n + e;
                        if (ne >= n_store) continue;
                        float x = acc[mi][ni][half_ * 2 + e];
                        if (EPI == 2) x += bias[ne] + Rp[(long)m * ldc + ne];
                        if (EPI == 3) x *= rscale;
                        Cf[(long)m * ldc + ne] = x;
                    }
                }
            }
        }
    }
}

// ---------------------------------------------------------------------------
// top-5 + softmax + gather + gate + residual + fused LN2 (one warp per pixel)
// redux.sync argmax; 32-bit hoisted gather offsets (register-neutral).
// ---------------------------------------------------------------------------
__global__ void topk_ln2_kernel(const float* __restrict__ logit_scale,
                                const float* __restrict__ alpha_p,
                                const float* __restrict__ g2,
                                const float* __restrict__ b2) {
    int warp = (blockIdx.x * blockDim.x + threadIdx.x) >> 5;
    int lane = threadIdx.x & 31;
    int b = warp >> 12;

    float ls = logit_scale[0];
    float scale = expf(fminf(fmaxf(ls, -2.f), 2.f)) * rsqrtf((float)CT);
    float alpha = alpha_p[0];

    const float* srow = g_sim + (long)warp * TT;
    float vals[4];
    #pragma unroll
    for (int i = 0; i < 4; i++) {
        int t = lane + 32 * i;
        vals[i] = (t < TT) ? srow[t] * scale : -INFINITY;
    }

    float wv[TOPM]; int wi_[TOPM];
    #pragma unroll
    for (int m = 0; m < TOPM; m++) {
        float bv = vals[0]; int bs = 0;
        #pragma unroll
        for (int i = 1; i < 4; i++)
            if (vals[i] > bv) { bv = vals[i]; bs = i; }
        uint32_t u = __float_as_uint(bv);
        uint32_t key = u ^ ((uint32_t)((int)u >> 31) | 0x80000000u);
        uint32_t wkey = __reduce_max_sync(0xffffffffu, key);
        uint32_t gidx = (key == wkey) ? (uint32_t)(lane + 32 * bs) : 0xffffffffu;
        uint32_t widx = __reduce_min_sync(0xffffffffu, gidx);
        wv[m] = __uint_as_float((wkey & 0x80000000u) ? (wkey ^ 0x80000000u) : ~wkey);
        wi_[m] = (int)widx;
        if ((widx & 31u) == (uint32_t)lane) vals[widx >> 5] = -INFINITY;
    }

    float mx = -INFINITY;
    #pragma unroll
    for (int m = 0; m < TOPM; m++) {
        if (g_pad[b * TT + wi_[m]]) wv[m] = -INFINITY;
        mx = fmaxf(mx, wv[m]);
    }
    float e[TOPM]; float se = 0.f;
    #pragma unroll
    for (int m = 0; m < TOPM; m++) {
        e[m] = (wv[m] == -INFINITY) ? 0.f : expf(wv[m] - mx);
        se += e[m];
    }
    float inv = 1.f / se;
    float ag = alpha * g_gate[warp];

    // 32-bit element offsets into g_v (fits: BB*TT*CV < 2^31); reuse wi_ slots
    uint32_t voff[TOPM]; float wgt[TOPM];
    #pragma unroll
    for (int m = 0; m < TOPM; m++) {
        voff[m] = (uint32_t)(b * TT + wi_[m]) * CV + lane;
        wgt[m] = e[m] * inv;
    }

    long rowoff = (long)warp * CV;
    float yv[8];
    #pragma unroll
    for (int j = 0; j < 8; j++) {
        int c32 = 32 * j;
        float a2 = 0.f;
        #pragma unroll
        for (int m = 0; m < TOPM; m++)
            a2 = fmaf(wgt[m], g_v[voff[m] + c32], a2);
        yv[j] = g_x[rowoff + lane + c32] + ag * a2;
    }
    // fused LayerNorm2
    float s = 0.f;
    #pragma unroll
    for (int j = 0; j < 8; j++) s += yv[j];
    float mean = wred(s) * (1.f / CV);
    float sq = 0.f;
    #pragma unroll
    for (int j = 0; j < 8; j++) { float d = yv[j] - mean; sq += d * d; }
    float rs = rsqrtf(wred(sq) * (1.f / CV) + 1e-5f);
    #pragma unroll
    for (int j = 0; j < 8; j++) {
        int c = lane + 32 * j;
        float y2 = (yv[j] - mean) * rs * g2[c] + b2[c];
        g_y2 [rowoff + c] = y2;
        g_y2t[rowoff + c] = __float2half_rn(y2);
    }
}

// ---------------------------------------------------------------------------
// Launch
// ---------------------------------------------------------------------------
static void* symaddr(const void* sym) {
    void* p = nullptr;
    cudaGetSymbolAddress(&p, sym);
    return p;
}

extern "C" void kernel_launch(void* const* d_in, const int* in_sizes, int n_in,
                              void* d_out, int out_size) {
    const float* visual = (const float*)d_in[0];
    const float* text   = (const float*)d_in[1];
    const float* ln1_g  = (const float*)d_in[2];
    const float* ln1_b  = (const float*)d_in[3];
    const float* qw     = (const float*)d_in[4];
    const float* qb     = (const float*)d_in[5];
    const float* vw     = (const float*)d_in[6];
    const float* vb     = (const float*)d_in[7];
    const float* gate_w = (const float*)d_in[8];
    const float* gate_b = (const float*)d_in[9];
    const float* lscale = (const float*)d_in[10];
    const float* alpha  = (const float*)d_in[11];
    const float* ln2_g  = (const float*)d_in[12];
    const float* ln2_b  = (const float*)d_in[13];
    const float* w1     = (const float*)d_in[14];
    const float* b1     = (const float*)d_in[15];
    const float* w2     = (const float*)d_in[16];
    const float* b2     = (const float*)d_in[17];
    float* out = (float*)d_out;

    __half* pq   = (__half*)symaddr(g_q);
    float*  pqss = (float*) symaddr(g_qss);
    __half* pkn  = (__half*)symaddr(g_kn);
    float*  ps   = (float*) symaddr(g_sim);
    float*  py2  = (float*) symaddr(g_y2);
    __half* py2t = (__half*)symaddr(g_y2t);
    __half* ph   = (__half*)symaddr(g_h);
    __half* pw1t = (__half*)symaddr(g_w1t);
    __half* pw2t = (__half*)symaddr(g_w2t);

    cudaFuncSetAttribute(qv_gemm,     cudaFuncAttributeMaxDynamicSharedMemorySize, SMEM_BYTES);
    cudaFuncSetAttribute(mma_gemm<1>, cudaFuncAttributeMaxDynamicSharedMemorySize, SMEM_BYTES);
    cudaFuncSetAttribute(mma_gemm<2>, cudaFuncAttributeMaxDynamicSharedMemorySize, SMEM_BYTES);
    cudaFuncSetAttribute(mma_gemm<3>, cudaFuncAttributeMaxDynamicSharedMemorySize, SMEM_BYTES);

    // 1. prep: weight transposes + LN1/gate + text prep (one launch)
    prep_kernel<<<TR_BLOCKS + LN1_BLOCKS + TEXT_BLOCKS, 256>>>(
        visual, text, qw, vw, w1, w2, ln1_g, ln1_b, gate_w, gate_b);

    // 2. Q (+qss) and V GEMMs fused in one launch
    qv_gemm<<<1024 + 14, 256, SMEM_BYTES>>>(qb, vb);

    // 3. sim = (q @ k^T) * rsqrt(sum qss)  (4096 x 100(->128) x 512, batched)
    mma_gemm<3><<<dim3(1, NN_/128, BB), 256, SMEM_BYTES>>>(
        pq, pkn, nullptr, pqss, ps, NN_, TPAD, CT, TT, TT,
        (long)NN_*CT, (long)TPAD*CT, (long)NN_*TT);

    // 4. top-5 + softmax + gather + gate + residual + LN2
    topk_ln2_kernel<<<ROWS/8, 256>>>(lscale, alpha, ln2_g, ln2_b);

    // 5. h = gelu(y2 @ w1 + b1) -> fp16   (32768 x 1024 x 256)
    mma_gemm<1><<<dim3(4*CV/128, ROWS/128, 1), 256, SMEM_BYTES>>>(
        py2t, pw1t, b1, nullptr, ph, ROWS, 4*CV, CV, 4*CV, 4*CV, 0, 0, 0);

    // 6. out = y2 + h @ w2 + b2 -> fp32   (32768 x 256 x 1024)
    mma_gemm<2><<<dim3(CV/128, ROWS/128, 1), 256, SMEM_BYTES>>>(
        ph, pw2t, b2, py2, out, ROWS, CV, 4*CV, CV, CV, 0, 0, 0);
}

// round 17
// speedup vs baseline: 1.0332x; 1.0180x over previous
#include <cuda_runtime.h>
#include <cuda_fp16.h>
#include <math.h>
#include <cstdint>

// ---------------------------------------------------------------------------
// Problem constants
// ---------------------------------------------------------------------------
#define BB   8
#define CV   256
#define CT   512
#define TT   100
#define TPAD 128            // padded text rows for sim GEMM
#define NN_  4096           // H*W
#define ROWS (BB*NN_)       // 32768
#define TOPM 5

// ---------------------------------------------------------------------------
// Scratch (static device globals: allocation-free)
// ---------------------------------------------------------------------------
__device__ float  g_x   [ROWS * CV];        // ln1 output (fp32, residual path)
__device__ __half g_xt  [ROWS * CV];        // ln1 output (fp16, GEMM A)
__device__ float  g_gate[ROWS];             // sigmoid gate
__device__ __half g_q   [ROWS * CT];        // x@qw+qb (fp16)
__device__ float  g_qss [16 * ROWS];        // partial sum-of-squares of q rows
__device__ __half g_kn  [BB * TPAD * CT];   // l2norm(text) fp16, padded
__device__ __half g_tr  [BB * TT * CT];     // text fp16 (V GEMM A)
__device__ float  g_v   [BB * TT * CV];     // text@vw+vb (fp32)
__device__ int    g_pad [BB * TT];
__device__ float  g_sim [ROWS * TT];        // (q.k) * 1/||q||
__device__ __half g_y2t [ROWS * CV];        // ln2 output (fp16: GEMM A + residual)
__device__ __half g_h   [ROWS * 4 * CV];    // gelu hidden (fp16)
// transposed fp16 weights ([N,K] K-major)
__device__ __half g_qwt [CT * CV];
__device__ __half g_vwt [CV * CT];
__device__ __half g_w1t [4*CV * CV];
__device__ __half g_w2t [CV * 4*CV];

// ---------------------------------------------------------------------------
// PTX helpers
// ---------------------------------------------------------------------------
__device__ __forceinline__ uint32_t smem_to_u32(const void* p) {
    uint32_t a;
    asm("{ .reg .u64 t; cvta.to.shared.u64 t, %1; cvt.u32.u64 %0, t; }"
        : "=r"(a) : "l"(p));
    return a;
}
__device__ __forceinline__ void cp16(uint32_t dst, const void* src, bool pred) {
    int sz = pred ? 16 : 0;
    asm volatile("cp.async.cg.shared.global [%0], [%1], 16, %2;\n"
        :: "r"(dst), "l"(src), "r"(sz));
}
__device__ __forceinline__ void mma16(float* c, const uint32_t* a, const uint32_t* b) {
    asm volatile(
        "mma.sync.aligned.m16n8k16.row.col.f32.f16.f16.f32 "
        "{%0,%1,%2,%3},{%4,%5,%6,%7},{%8,%9},{%0,%1,%2,%3};"
        : "+f"(c[0]), "+f"(c[1]), "+f"(c[2]), "+f"(c[3])
        : "r"(a[0]), "r"(a[1]), "r"(a[2]), "r"(a[3]), "r"(b[0]), "r"(b[1]));
}
__device__ __forceinline__ void ldsm4(uint32_t* r, uint32_t addr) {
    asm volatile("ldmatrix.sync.aligned.m8n8.x4.shared.b16 {%0,%1,%2,%3}, [%4];"
        : "=r"(r[0]), "=r"(r[1]), "=r"(r[2]), "=r"(r[3]) : "r"(addr));
}
__device__ __forceinline__ float wred(float v) {
    #pragma unroll
    for (int o = 16; o; o >>= 1) v += __shfl_xor_sync(0xffffffffu, v, o);
    return v;
}

// ---------------------------------------------------------------------------
// Prep kernel: blocks [0,768) weight transposes, [768, 768+4096) LN1+gate,
// then 128 text-prep blocks. 256 threads each.
// ---------------------------------------------------------------------------
#define TR_BLOCKS 768
#define LN1_BLOCKS (ROWS / 8)
#define TEXT_BLOCKS (BB * TPAD / 8)

__device__ __forceinline__ void tr_tile(const float* __restrict__ src,
                                        __half* __restrict__ dst,
                                        int Kd, int Nd, int bx, int by,
                                        float (*t)[33], int x, int y) {
    int k0 = by * 32, n0 = bx * 32;
    #pragma unroll
    for (int i = 0; i < 32; i += 8)
        t[y + i][x] = src[(long)(k0 + y + i) * Nd + n0 + x];
    __syncthreads();
    #pragma unroll
    for (int i = 0; i < 32; i += 8)
        dst[(long)(n0 + y + i) * Kd + k0 + x] = __float2half_rn(t[x][y + i]);
}

__global__ void prep_kernel(const float* __restrict__ vis,
                            const float* __restrict__ text,
                            const float* __restrict__ qw, const float* __restrict__ vw,
                            const float* __restrict__ w1, const float* __restrict__ w2,
                            const float* __restrict__ g, const float* __restrict__ b,
                            const float* __restrict__ gw, const float* __restrict__ gbp) {
    __shared__ float t[32][33];
    int lane = threadIdx.x & 31;
    if (blockIdx.x < TR_BLOCKS) {
        int id = blockIdx.x;
        int x = threadIdx.x & 31, y = threadIdx.x >> 5;
        if (id < 128)       tr_tile(qw, g_qwt, CV, CT, id & 15, id >> 4, t, x, y);
        else if (id < 256)  { id -= 128; tr_tile(vw, g_vwt, CT, CV, id & 7, id >> 3, t, x, y); }
        else if (id < 512)  { id -= 256; tr_tile(w1, g_w1t, CV, 4*CV, id & 31, id >> 5, t, x, y); }
        else                { id -= 512; tr_tile(w2, g_w2t, 4*CV, CV, id & 7, id >> 3, t, x, y); }
    } else if (blockIdx.x < TR_BLOCKS + LN1_BLOCKS) {
        int row = (blockIdx.x - TR_BLOCKS) * 8 + (threadIdx.x >> 5);
        const float4* vr = (const float4*)(vis + (long)row * CV);
        float4 v0 = vr[lane * 2], v1 = vr[lane * 2 + 1];
        float s = v0.x + v0.y + v0.z + v0.w + v1.x + v1.y + v1.z + v1.w;
        float mean = wred(s) * (1.f / CV);
        float d[8] = {v0.x-mean, v0.y-mean, v0.z-mean, v0.w-mean,
                      v1.x-mean, v1.y-mean, v1.z-mean, v1.w-mean};
        float sq = 0.f;
        #pragma unroll
        for (int e = 0; e < 8; e++) sq += d[e] * d[e];
        float rs = rsqrtf(wred(sq) * (1.f / CV) + 1e-5f);
        const float4* gr = (const float4*)g;  const float4* br = (const float4*)b;
        const float4* gwr = (const float4*)gw;
        float4 ga = gr[lane*2], gb4 = gr[lane*2+1], ba = br[lane*2], bb4 = br[lane*2+1];
        float4 wa = gwr[lane*2], wb = gwr[lane*2+1];
        float xv[8];
        xv[0]=d[0]*rs*ga.x+ba.x; xv[1]=d[1]*rs*ga.y+ba.y; xv[2]=d[2]*rs*ga.z+ba.z; xv[3]=d[3]*rs*ga.w+ba.w;
        xv[4]=d[4]*rs*gb4.x+bb4.x; xv[5]=d[5]*rs*gb4.y+bb4.y; xv[6]=d[6]*rs*gb4.z+bb4.z; xv[7]=d[7]*rs*gb4.w+bb4.w;
        float4* xo = (float4*)(g_x + (long)row * CV);
        xo[lane*2]   = make_float4(xv[0],xv[1],xv[2],xv[3]);
        xo[lane*2+1] = make_float4(xv[4],xv[5],xv[6],xv[7]);
        __half2* xto = (__half2*)(g_xt + (long)row * CV);
        xto[lane*4+0] = __floats2half2_rn(xv[0], xv[1]);
        xto[lane*4+1] = __floats2half2_rn(xv[2], xv[3]);
        xto[lane*4+2] = __floats2half2_rn(xv[4], xv[5]);
        xto[lane*4+3] = __floats2half2_rn(xv[6], xv[7]);
        float gp = xv[0]*wa.x+xv[1]*wa.y+xv[2]*wa.z+xv[3]*wa.w
                 + xv[4]*wb.x+xv[5]*wb.y+xv[6]*wb.z+xv[7]*wb.w;
        gp = wred(gp);
        if (lane == 0) g_gate[row] = 1.f / (1.f + expf(-(gp + gbp[0])));
    } else {
        int p = (blockIdx.x - TR_BLOCKS - LN1_BLOCKS) * 8 + (threadIdx.x >> 5);
        int bz = p >> 7, tt = p & (TPAD - 1);
        __half2* ko = (__half2*)(g_kn + (long)p * CT);
        if (tt >= TT) {
            #pragma unroll
            for (int j = 0; j < 4; j++) {
                ko[2*(lane + j*32)]     = __floats2half2_rn(0.f, 0.f);
                ko[2*(lane + j*32) + 1] = __floats2half2_rn(0.f, 0.f);
            }
            return;
        }
        const float4* tr = (const float4*)(text + ((long)bz * TT + tt) * CT);
        __half2* tro = (__half2*)(g_tr + ((long)bz * TT + tt) * CT);
        float4 v[4]; float sa = 0.f, ss = 0.f;
        #pragma unroll
        for (int j = 0; j < 4; j++) {
            v[j] = tr[lane + j * 32];
            sa += fabsf(v[j].x)+fabsf(v[j].y)+fabsf(v[j].z)+fabsf(v[j].w);
            ss += v[j].x*v[j].x + v[j].y*v[j].y + v[j].z*v[j].z + v[j].w*v[j].w;
        }
        sa = wred(sa); ss = wred(ss);
        if (lane == 0) g_pad[bz * TT + tt] = (sa <= 1e-6f) ? 1 : 0;
        float inv = 1.f / fmaxf(sqrtf(ss), 1e-6f);
        #pragma unroll
        for (int j = 0; j < 4; j++) {
            ko[2*(lane + j*32)]     = __floats2half2_rn(v[j].x*inv, v[j].y*inv);
            ko[2*(lane + j*32) + 1] = __floats2half2_rn(v[j].z*inv, v[j].w*inv);
            tro[2*(lane + j*32)]     = __floats2half2_rn(v[j].x, v[j].y);
            tro[2*(lane + j*32) + 1] = __floats2half2_rn(v[j].z, v[j].w);
        }
    }
}

// ---------------------------------------------------------------------------
// Shared GEMM machinery. CTA 128x128, BK=64, 8 warps (2x4), warp 64x32.
// 3-stage cp.async, one __syncthreads per chunk.
// Pointer-increment addressing: all per-chunk address math hoisted.
// ---------------------------------------------------------------------------
#define SPITCH 72                         // halfs per smem row (144 B)
#define TILE_H (128 * SPITCH)
#define STAGE_H (2 * TILE_H)
#define NSTAGE 3
#define SMEM_BYTES (NSTAGE * STAGE_H * 2) // 110592 bytes

struct FragCtx {
    uint32_t sbase, aOff, bOff;
    int tid, wm, wn, lr, lc;
};

__device__ __forceinline__ void gemm_mainloop(
    const __half* __restrict__ A, const __half* __restrict__ Bt,
    int M, int N, int K, int m0, int n0, const FragCtx& fc,
    float acc[4][4][4])
{
    int tid = fc.tid;
    int nc = K >> 6;

    // hoisted per-thread load decode
    int r0 = tid >> 3;
    int k8 = (tid & 7) * 8;
    const __half* aPtr = A + (long)(m0 + r0) * K + k8;
    const __half* bPtr = Bt + (long)(n0 + r0) * K + k8;
    const long dK = (long)32 * K;
    bool pa[4], pb[4];
    uint32_t aoff[4], boff[4];
    #pragma unroll
    for (int i = 0; i < 4; i++) {
        pa[i] = (m0 + r0 + 32 * i) < M;
        pb[i] = (n0 + r0 + 32 * i) < N;
        aoff[i] = (uint32_t)((r0 + 32 * i) * SPITCH + k8) * 2u;
        boff[i] = aoff[i] + (uint32_t)TILE_H * 2u;
    }

    auto load_chunk = [&](int buf) {
        uint32_t s0 = fc.sbase + (uint32_t)(buf * STAGE_H) * 2u;
        #pragma unroll
        for (int i = 0; i < 4; i++)
            cp16(s0 + aoff[i], aPtr + dK * i, pa[i]);
        #pragma unroll
        for (int i = 0; i < 4; i++)
            cp16(s0 + boff[i], bPtr + dK * i, pb[i]);
        asm volatile("cp.async.commit_group;\n" ::: "memory");
        aPtr += 64; bPtr += 64;
    };

    load_chunk(0);
    if (nc > 1) load_chunk(1);
    else        asm volatile("cp.async.commit_group;\n" ::: "memory");

    for (int c = 0; c < nc; c++) {
        int buf = c % NSTAGE;
        asm volatile("cp.async.wait_group 1;\n" ::: "memory");
        __syncthreads();

        if (c + 2 < nc) load_chunk((c + 2) % NSTAGE);
        else asm volatile("cp.async.commit_group;\n" ::: "memory");

        uint32_t aBase = fc.sbase + (uint32_t)(buf * STAGE_H) * 2u + fc.aOff;
        uint32_t bBase = fc.sbase + (uint32_t)(buf * STAGE_H + TILE_H) * 2u + fc.bOff;

        #pragma unroll
        for (int ks = 0; ks < 4; ks++) {
            uint32_t kbyte = (uint32_t)(ks * 16 * 2);
            uint32_t af[4][4], bf[2][4];
            #pragma unroll
            for (int mi = 0; mi < 4; mi++)
                ldsm4(af[mi], aBase + (uint32_t)(mi * 16 * SPITCH * 2) + kbyte);
            #pragma unroll
            for (int np = 0; np < 2; np++)
                ldsm4(bf[np], bBase + (uint32_t)(np * 16 * SPITCH * 2) + kbyte);
            #pragma unroll
            for (int mi = 0; mi < 4; mi++)
                #pragma unroll
                for (int ni = 0; ni < 4; ni++)
                    mma16(acc[mi][ni], af[mi], &bf[ni >> 1][(ni & 1) * 2]);
        }
    }
}

__device__ __forceinline__ FragCtx make_ctx(uint32_t sbase) {
    FragCtx fc;
    int tid = threadIdx.x, wid = tid >> 5, lane = tid & 31;
    fc.tid = tid;
    fc.wm = wid & 1; fc.wn = wid >> 1;
    fc.lr = lane >> 2; fc.lc = lane & 3;
    int sel = lane >> 3, l8 = lane & 7;
    fc.sbase = sbase;
    fc.aOff = (uint32_t)(((fc.wm * 64 + (sel & 1) * 8 + l8) * SPITCH + (sel >> 1) * 8) * 2);
    fc.bOff = (uint32_t)(((fc.wn * 32 + (sel >> 1) * 8 + l8) * SPITCH + (sel & 1) * 8) * 2);
    return fc;
}

// ---------------------------------------------------------------------------
// Fused Q + V GEMM.
// ---------------------------------------------------------------------------
__global__ __launch_bounds__(256, 2) void qv_gemm(
    const float* __restrict__ qb, const float* __restrict__ vb)
{
    extern __shared__ __half smem[];
    FragCtx fc = make_ctx(smem_to_u32(smem));
    float acc[4][4][4];
    #pragma unroll
    for (int i = 0; i < 4; i++)
        #pragma unroll
        for (int j = 0; j < 4; j++)
            #pragma unroll
            for (int e = 0; e < 4; e++) acc[i][j][e] = 0.f;

    if (blockIdx.x < 1024) {
        int bx = blockIdx.x & 3, by = blockIdx.x >> 2;
        int m0 = by * 128, n0 = bx * 128;
        gemm_mainloop(g_xt, g_qwt, ROWS, CT, CV, m0, n0, fc, acc);
        #pragma unroll
        for (int mi = 0; mi < 4; mi++) {
            #pragma unroll
            for (int half_ = 0; half_ < 2; half_++) {
                int m = m0 + fc.wm * 64 + mi * 16 + fc.lr + half_ * 8;
                float ps = 0.f;
                #pragma unroll
                for (int ni = 0; ni < 4; ni++) {
                    int n = n0 + fc.wn * 32 + ni * 8 + 2 * fc.lc;
                    float x0 = acc[mi][ni][half_ * 2 + 0] + qb[n];
                    float x1 = acc[mi][ni][half_ * 2 + 1] + qb[n + 1];
                    ps += x0 * x0 + x1 * x1;
                    *(__half2*)(g_q + (long)m * CT + n) = __floats2half2_rn(x0, x1);
                }
                ps += __shfl_xor_sync(0xffffffffu, ps, 1);
                ps += __shfl_xor_sync(0xffffffffu, ps, 2);
                if (fc.lc == 0)
                    g_qss[(long)(bx * 4 + fc.wn) * ROWS + m] = ps;
            }
        }
    } else {
        int id2 = blockIdx.x - 1024;
        int bx = id2 & 1, by = id2 >> 1;
        int m0 = by * 128, n0 = bx * 128;
        gemm_mainloop(g_tr, g_vwt, BB * TT, CV, CT, m0, n0, fc, acc);
        #pragma unroll
        for (int mi = 0; mi < 4; mi++) {
            #pragma unroll
            for (int half_ = 0; half_ < 2; half_++) {
                int m = m0 + fc.wm * 64 + mi * 16 + fc.lr + half_ * 8;
                if (m >= BB * TT) continue;
                #pragma unroll
                for (int ni = 0; ni < 4; ni++) {
                    int n = n0 + fc.wn * 32 + ni * 8 + 2 * fc.lc;
                    g_v[(long)m * CV + n]     = acc[mi][ni][half_ * 2 + 0] + vb[n];
                    g_v[(long)m * CV + n + 1] = acc[mi][ni][half_ * 2 + 1] + vb[n + 1];
                }
            }
        }
    }
}

// ---------------------------------------------------------------------------
// mma_gemm template: sim (EPI 3), MLP1 (EPI 1), MLP2 (EPI 2)
// EPI 2 residual comes from g_y2t (fp16) directly.
// ---------------------------------------------------------------------------
template<int EPI>
__global__ __launch_bounds__(256, 2) void mma_gemm(
    const __half* __restrict__ A, const __half* __restrict__ Bt,
    const float* __restrict__ bias, const float* __restrict__ R,
    void* __restrict__ Cv, int M, int N, int K,
    int ldc, int n_store, long sA, long sB, long sC)
{
    extern __shared__ __half smem[];
    FragCtx fc = make_ctx(smem_to_u32(smem));

    A  += (long)blockIdx.z * sA;
    Bt += (long)blockIdx.z * sB;
    float*  Cf = (float*)Cv  + (long)blockIdx.z * sC;
    __half* Ch = (__half*)Cv + (long)blockIdx.z * sC;
    const float* Rp = (EPI == 3) ? (R + (long)blockIdx.z * M) : R;

    int m0 = blockIdx.y * 128, n0 = blockIdx.x * 128;

    float acc[4][4][4];
    #pragma unroll
    for (int i = 0; i < 4; i++)
        #pragma unroll
        for (int j = 0; j < 4; j++)
            #pragma unroll
            for (int e = 0; e < 4; e++) acc[i][j][e] = 0.f;

    gemm_mainloop(A, Bt, M, N, K, m0, n0, fc, acc);

    // ---- EPI 3: stage 16 qss partials per row into smem scratch ----
    float* qs = (float*)smem;
    if (EPI == 3) {
        __syncthreads();
        #pragma unroll
        for (int i = 0; i < 8; i++) {
            int idx = fc.tid + 256 * i;         // 0..2047
            int p = idx >> 7, row = idx & 127;
            qs[row * 17 + p] = Rp[(long)p * ROWS + m0 + row];
        }
        __syncthreads();
    }

    #pragma unroll
    for (int mi = 0; mi < 4; mi++) {
        #pragma unroll
        for (int half_ = 0; half_ < 2; half_++) {
            int m = m0 + fc.wm * 64 + mi * 16 + fc.lr + half_ * 8;
            if (m >= M) continue;
            float rscale = 0.f;
            if (EPI == 3) {
                float ss = 0.f;
                #pragma unroll
                for (int i = 0; i < 16; i++) ss += qs[(m - m0) * 17 + i];
                rscale = 1.f / fmaxf(sqrtf(ss), 1e-6f);
            }
            #pragma unroll
            for (int ni = 0; ni < 4; ni++) {
                int n = n0 + fc.wn * 32 + ni * 8 + 2 * fc.lc;
                if (EPI == 1) {
                    float x0 = acc[mi][ni][half_ * 2 + 0] + bias[n];
                    float x1 = acc[mi][ni][half_ * 2 + 1] + bias[n + 1];
                    x0 = 0.5f * x0 * (1.f + erff(x0 * 0.70710678118654752f));
                    x1 = 0.5f * x1 * (1.f + erff(x1 * 0.70710678118654752f));
                    *(__half2*)(Ch + (long)m * ldc + n) = __floats2half2_rn(x0, x1);
                } else if (EPI == 2) {
                    // residual from fp16 g_y2t
                    __half2 r2 = *(const __half2*)(g_y2t + (long)m * ldc + n);
                    float2 rf = __half22float2(r2);
                    Cf[(long)m * ldc + n]     = acc[mi][ni][half_ * 2 + 0] + bias[n]     + rf.x;
                    Cf[(long)m * ldc + n + 1] = acc[mi][ni][half_ * 2 + 1] + bias[n + 1] + rf.y;
                } else {
                    #pragma unroll
                    for (int e = 0; e < 2; e++) {
                        int ne = n + e;
                        if (ne >= n_store) continue;
                        float x = acc[mi][ni][half_ * 2 + e];
                        if (EPI == 3) x *= rscale;
                        Cf[(long)m * ldc + ne] = x;
                    }
                }
            }
        }
    }
}

// ---------------------------------------------------------------------------
// top-5 + softmax + gather + gate + residual + fused LN2 (one warp per pixel)
// redux.sync argmax; 32-bit hoisted gather offsets; fp16-only LN2 output.
// ---------------------------------------------------------------------------
__global__ void topk_ln2_kernel(const float* __restrict__ logit_scale,
                                const float* __restrict__ alpha_p,
                                const float* __restrict__ g2,
                                const float* __restrict__ b2) {
    int warp = (blockIdx.x * blockDim.x + threadIdx.x) >> 5;
    int lane = threadIdx.x & 31;
    int b = warp >> 12;

    float ls = logit_scale[0];
    float scale = expf(fminf(fmaxf(ls, -2.f), 2.f)) * rsqrtf((float)CT);
    float alpha = alpha_p[0];

    const float* srow = g_sim + (long)warp * TT;
    float vals[4];
    #pragma unroll
    for (int i = 0; i < 4; i++) {
        int t = lane + 32 * i;
        vals[i] = (t < TT) ? srow[t] * scale : -INFINITY;
    }

    float wv[TOPM]; int wi_[TOPM];
    #pragma unroll
    for (int m = 0; m < TOPM; m++) {
        float bv = vals[0]; int bs = 0;
        #pragma unroll
        for (int i = 1; i < 4; i++)
            if (vals[i] > bv) { bv = vals[i]; bs = i; }
        uint32_t u = __float_as_uint(bv);
        uint32_t key = u ^ ((uint32_t)((int)u >> 31) | 0x80000000u);
        uint32_t wkey = __reduce_max_sync(0xffffffffu, key);
        uint32_t gidx = (key == wkey) ? (uint32_t)(lane + 32 * bs) : 0xffffffffu;
        uint32_t widx = __reduce_min_sync(0xffffffffu, gidx);
        wv[m] = __uint_as_float((wkey & 0x80000000u) ? (wkey ^ 0x80000000u) : ~wkey);
        wi_[m] = (int)widx;
        if ((widx & 31u) == (uint32_t)lane) vals[widx >> 5] = -INFINITY;
    }

    float mx = -INFINITY;
    #pragma unroll
    for (int m = 0; m < TOPM; m++) {
        if (g_pad[b * TT + wi_[m]]) wv[m] = -INFINITY;
        mx = fmaxf(mx, wv[m]);
    }
    float e[TOPM]; float se = 0.f;
    #pragma unroll
    for (int m = 0; m < TOPM; m++) {
        e[m] = (wv[m] == -INFINITY) ? 0.f : expf(wv[m] - mx);
        se += e[m];
    }
    float inv = 1.f / se;
    float ag = alpha * g_gate[warp];

    // 32-bit element offsets into g_v (fits: BB*TT*CV < 2^31)
    uint32_t voff[TOPM]; float wgt[TOPM];
    #pragma unroll
    for (int m = 0; m < TOPM; m++) {
        voff[m] = (uint32_t)(b * TT + wi_[m]) * CV + lane;
        wgt[m] = e[m] * inv;
    }

    long rowoff = (long)warp * CV;
    float yv[8];
    #pragma unroll
    for (int j = 0; j < 8; j++) {
        int c32 = 32 * j;
        float a2 = 0.f;
        #pragma unroll
        for (int m = 0; m < TOPM; m++)
            a2 = fmaf(wgt[m], g_v[voff[m] + c32], a2);
        yv[j] = g_x[rowoff + lane + c32] + ag * a2;
    }
    // fused LayerNorm2
    float s = 0.f;
    #pragma unroll
    for (int j = 0; j < 8; j++) s += yv[j];
    float mean = wred(s) * (1.f / CV);
    float sq = 0.f;
    #pragma unroll
    for (int j = 0; j < 8; j++) { float d = yv[j] - mean; sq += d * d; }
    float rs = rsqrtf(wred(sq) * (1.f / CV) + 1e-5f);
    #pragma unroll
    for (int j = 0; j < 8; j++) {
        int c = lane + 32 * j;
        float y2 = (yv[j] - mean) * rs * g2[c] + b2[c];
        g_y2t[rowoff + c] = __float2half_rn(y2);
    }
}

// ---------------------------------------------------------------------------
// Launch
// ---------------------------------------------------------------------------
static void* symaddr(const void* sym) {
    void* p = nullptr;
    cudaGetSymbolAddress(&p, sym);
    return p;
}

extern "C" void kernel_launch(void* const* d_in, const int* in_sizes, int n_in,
                              void* d_out, int out_size) {
    const float* visual = (const float*)d_in[0];
    const float* text   = (const float*)d_in[1];
    const float* ln1_g  = (const float*)d_in[2];
    const float* ln1_b  = (const float*)d_in[3];
    const float* qw     = (const float*)d_in[4];
    const float* qb     = (const float*)d_in[5];
    const float* vw     = (const float*)d_in[6];
    const float* vb     = (const float*)d_in[7];
    const float* gate_w = (const float*)d_in[8];
    const float* gate_b = (const float*)d_in[9];
    const float* lscale = (const float*)d_in[10];
    const float* alpha  = (const float*)d_in[11];
    const float* ln2_g  = (const float*)d_in[12];
    const float* ln2_b  = (const float*)d_in[13];
    const float* w1     = (const float*)d_in[14];
    const float* b1     = (const float*)d_in[15];
    const float* w2     = (const float*)d_in[16];
    const float* b2     = (const float*)d_in[17];
    float* out = (float*)d_out;

    __half* pq   = (__half*)symaddr(g_q);
    float*  pqss = (float*) symaddr(g_qss);
    __half* pkn  = (__half*)symaddr(g_kn);
    float*  ps   = (float*) symaddr(g_sim);
    __half* py2t = (__half*)symaddr(g_y2t);
    __half* ph   = (__half*)symaddr(g_h);
    __half* pw1t = (__half*)symaddr(g_w1t);
    __half* pw2t = (__half*)symaddr(g_w2t);

    cudaFuncSetAttribute(qv_gemm,     cudaFuncAttributeMaxDynamicSharedMemorySize, SMEM_BYTES);
    cudaFuncSetAttribute(mma_gemm<1>, cudaFuncAttributeMaxDynamicSharedMemorySize, SMEM_BYTES);
    cudaFuncSetAttribute(mma_gemm<2>, cudaFuncAttributeMaxDynamicSharedMemorySize, SMEM_BYTES);
    cudaFuncSetAttribute(mma_gemm<3>, cudaFuncAttributeMaxDynamicSharedMemorySize, SMEM_BYTES);

    // 1. prep: weight transposes + LN1/gate + text prep (one launch)
    prep_kernel<<<TR_BLOCKS + LN1_BLOCKS + TEXT_BLOCKS, 256>>>(
        visual, text, qw, vw, w1, w2, ln1_g, ln1_b, gate_w, gate_b);

    // 2. Q (+qss) and V GEMMs fused in one launch
    qv_gemm<<<1024 + 14, 256, SMEM_BYTES>>>(qb, vb);

    // 3. sim = (q @ k^T) * rsqrt(sum qss)  (4096 x 100(->128) x 512, batched)
    mma_gemm<3><<<dim3(1, NN_/128, BB), 256, SMEM_BYTES>>>(
        pq, pkn, nullptr, pqss, ps, NN_, TPAD, CT, TT, TT,
        (long)NN_*CT, (long)TPAD*CT, (long)NN_*TT);

    // 4. top-5 + softmax + gather + gate + residual + LN2 (fp16 out only)
    topk_ln2_kernel<<<ROWS/8, 256>>>(lscale, alpha, ln2_g, ln2_b);

    // 5. h = gelu(y2 @ w1 + b1) -> fp16   (32768 x 1024 x 256)
    mma_gemm<1><<<dim3(4*CV/128, ROWS/128, 1), 256, SMEM_BYTES>>>(
        py2t, pw1t, b1, nullptr, ph, ROWS, 4*CV, CV, 4*CV, 4*CV, 0, 0, 0);

    // 6. out = y2(fp16) + h @ w2 + b2 -> fp32   (32768 x 256 x 1024)
    mma_gemm<2><<<dim3(CV/128, ROWS/128, 1), 256, SMEM_BYTES>>>(
        ph, pw2t, b2, nullptr, out, ROWS, CV, 4*CV, CV, CV, 0, 0, 0);
}